// round 5
// baseline (speedup 1.0000x reference)
#include <cuda_runtime.h>
#include <cstdint>

#define BB 4
#define HH 8
#define SS 2048
#define DD 512
#define DH 64
#define TOPK 10

// Scratch: Q/K/V in [b][h][s][dh] layout (head-major), fp32.
__device__ float g_Q[BB*HH*SS*DH];
__device__ float g_K[BB*HH*SS*DH];
__device__ float g_V[BB*HH*SS*DH];

__device__ __forceinline__ float neg_inf() { return __int_as_float(0xff800000); }

// ---------------------------------------------------------------------------
// Kernel 1: Y = x @ W^T + b for W in {Wq,Wk,Wv}; scatter into [b][h][s][dh].
// Plain fp32 FMA, strictly serial ascending-k accumulation per output
// (matches cublas/Eigen SIMT sgemm accumulation order).
// 64x64 output tile, K-tile 16, 256 threads, 4x4 register blocking.
// ---------------------------------------------------------------------------
__global__ __launch_bounds__(256) void qkv_kernel(
    const float* __restrict__ x,
    const float* __restrict__ Wq, const float* __restrict__ bq,
    const float* __restrict__ Wk, const float* __restrict__ bk,
    const float* __restrict__ Wv, const float* __restrict__ bv)
{
    const int which = blockIdx.z;
    const float* __restrict__ W    = (which == 0) ? Wq : (which == 1) ? Wk : Wv;
    const float* __restrict__ bias = (which == 0) ? bq : (which == 1) ? bk : bv;
    float* __restrict__ out        = (which == 0) ? g_Q : (which == 1) ? g_K : g_V;

    __shared__ float As[16][68];   // [k][m], padded
    __shared__ float Bs[16][68];   // [k][n], padded

    const int tid = threadIdx.x;
    const int tx  = tid & 15;       // 0..15 -> n
    const int ty  = tid >> 4;       // 0..15 -> m
    const int m0  = blockIdx.y * 64;
    const int n0  = blockIdx.x * 64;   // one head per n-tile (DH==64)

    const int lrow = tid >> 2;      // 0..63
    const int lk4  = tid & 3;       // 0..3  (float4 index within 16 k's)

    float c[4][4];
    #pragma unroll
    for (int i = 0; i < 4; ++i)
        #pragma unroll
        for (int j = 0; j < 4; ++j) c[i][j] = 0.f;

    for (int kt = 0; kt < DD / 16; ++kt) {
        float4 av = *(const float4*)&x[(size_t)(m0 + lrow) * DD + kt * 16 + lk4 * 4];
        float4 bv4 = *(const float4*)&W[(size_t)(n0 + lrow) * DD + kt * 16 + lk4 * 4];
        __syncthreads();
        As[lk4 * 4 + 0][lrow] = av.x;
        As[lk4 * 4 + 1][lrow] = av.y;
        As[lk4 * 4 + 2][lrow] = av.z;
        As[lk4 * 4 + 3][lrow] = av.w;
        Bs[lk4 * 4 + 0][lrow] = bv4.x;
        Bs[lk4 * 4 + 1][lrow] = bv4.y;
        Bs[lk4 * 4 + 2][lrow] = bv4.z;
        Bs[lk4 * 4 + 3][lrow] = bv4.w;
        __syncthreads();
        // k ascending; each c[i][j] is one serial FMA chain over all 512 k.
        #pragma unroll
        for (int k = 0; k < 16; ++k) {
            float4 a  = *(const float4*)&As[k][ty * 4];
            float4 b4 = *(const float4*)&Bs[k][tx * 4];
            c[0][0] = fmaf(a.x, b4.x, c[0][0]); c[0][1] = fmaf(a.x, b4.y, c[0][1]);
            c[0][2] = fmaf(a.x, b4.z, c[0][2]); c[0][3] = fmaf(a.x, b4.w, c[0][3]);
            c[1][0] = fmaf(a.y, b4.x, c[1][0]); c[1][1] = fmaf(a.y, b4.y, c[1][1]);
            c[1][2] = fmaf(a.y, b4.z, c[1][2]); c[1][3] = fmaf(a.y, b4.w, c[1][3]);
            c[2][0] = fmaf(a.z, b4.x, c[2][0]); c[2][1] = fmaf(a.z, b4.y, c[2][1]);
            c[2][2] = fmaf(a.z, b4.z, c[2][2]); c[2][3] = fmaf(a.z, b4.w, c[2][3]);
            c[3][0] = fmaf(a.w, b4.x, c[3][0]); c[3][1] = fmaf(a.w, b4.y, c[3][1]);
            c[3][2] = fmaf(a.w, b4.z, c[3][2]); c[3][3] = fmaf(a.w, b4.w, c[3][3]);
        }
    }

    float4 biasv = *(const float4*)&bias[n0 + tx * 4];
    const int head = blockIdx.x;
    #pragma unroll
    for (int i = 0; i < 4; ++i) {
        int m  = m0 + ty * 4 + i;
        int b_ = m >> 11;        // m / 2048
        int s_ = m & 2047;
        float4 o;
        o.x = c[i][0] + biasv.x;
        o.y = c[i][1] + biasv.y;
        o.z = c[i][2] + biasv.z;
        o.w = c[i][3] + biasv.w;
        *(float4*)&out[(size_t)(((b_ * HH + head) * SS) + s_) * DH + tx * 4] = o;
    }
}

// ---------------------------------------------------------------------------
// Kernel 2: per (b,h, 32-q-row tile): stream K tiles through smem; each score
// is a SINGLE serial ascending-d FMA chain (8 independent chains interleaved
// for ILP); per-thread top-10 (8 threads/row), merge, softmax over 10,
// scatter attn (rest pre-zeroed by memset), context row.
// Row mapping row = 8*i + slot -> warp's 8 slots read CONSECUTIVE Ks rows
// (stride 68 % 32 banks = 4): conflict-free LDS with 4-way broadcast.
// ---------------------------------------------------------------------------
__global__ __launch_bounds__(256) void attn_kernel(
    float* __restrict__ out_ctx, float* __restrict__ out_attn)
{
    const int qt  = blockIdx.x;     // 0..63
    const int bh  = blockIdx.y;     // 0..31
    const int tid = threadIdx.x;
    const int r    = tid >> 3;      // q row within tile, 0..31
    const int slot = tid & 7;       // 0..7

    __shared__ float Ks[64 * 68];       // K tile, padded rows
    __shared__ float cv[256 * TOPK];    // per-thread candidates (values)
    __shared__ int   ci[256 * TOPK];    // per-thread candidates (indices)
    __shared__ float pb[32 * TOPK];     // per-row: merged scores -> probs
    __shared__ int   tix[32 * TOPK];    // per-row: merged indices

    const float* __restrict__ Qb = g_Q + (size_t)bh * SS * DH;
    const float* __restrict__ Kb = g_K + (size_t)bh * SS * DH;
    const float* __restrict__ Vb = g_V + (size_t)bh * SS * DH;

    // Stage Q tile (32 x 64) into Ks buffer, then pull own row into regs.
    {
        #pragma unroll
        for (int u = 0; u < 2; ++u) {
            int idx = tid * 2 + u;          // 0..511 float4s
            int row = idx >> 4, c4 = idx & 15;
            float4 v = *(const float4*)&Qb[(size_t)(qt * 32 + row) * DH + c4 * 4];
            *(float4*)&Ks[row * 68 + c4 * 4] = v;
        }
    }
    __syncthreads();
    // 0.125 folded into q: power of two, bit-exact commute with serial FMA
    // chain vs scaling the summed score afterwards.
    float4 qv[16];
    #pragma unroll
    for (int j = 0; j < 16; ++j) {
        float4 v = *(const float4*)&Ks[r * 68 + j * 4];
        qv[j].x = v.x * 0.125f; qv[j].y = v.y * 0.125f;
        qv[j].z = v.z * 0.125f; qv[j].w = v.w * 0.125f;
    }
    __syncthreads();

    float tv[TOPK];
    int   tid_[TOPK];
    #pragma unroll
    for (int t = 0; t < TOPK; ++t) { tv[t] = neg_inf(); tid_[t] = 0x7FFFFFFF; }

    for (int kt = 0; kt < SS / 64; ++kt) {
        #pragma unroll
        for (int u = 0; u < 4; ++u) {
            int idx = tid + 256 * u;        // 0..1023 float4s
            int row = idx >> 4, c4 = idx & 15;
            *(float4*)&Ks[row * 68 + c4 * 4] =
                *(const float4*)&Kb[(size_t)(kt * 64 + row) * DH + c4 * 4];
        }
        __syncthreads();

        // 8 serial score chains, d ascending; j outer keeps each chain serial,
        // i inner gives 8-way ILP.
        float acc[8];
        #pragma unroll
        for (int i = 0; i < 8; ++i) acc[i] = 0.f;
        #pragma unroll
        for (int j = 0; j < 16; ++j) {
            #pragma unroll
            for (int i = 0; i < 8; ++i) {
                float4 kf = *(const float4*)&Ks[(i * 8 + slot) * 68 + j * 4];
                acc[i] = fmaf(qv[j].x, kf.x, acc[i]);
                acc[i] = fmaf(qv[j].y, kf.y, acc[i]);
                acc[i] = fmaf(qv[j].z, kf.z, acc[i]);
                acc[i] = fmaf(qv[j].w, kf.w, acc[i]);
            }
        }

        #pragma unroll
        for (int i = 0; i < 8; ++i) {
            float sc = acc[i];
            int kidx = kt * 64 + i * 8 + slot;
            if (sc > tv[TOPK - 1]) {
                float vs = sc; int is = kidx;
                #pragma unroll
                for (int t = 0; t < TOPK; ++t) {
                    if (vs > tv[t]) {
                        float tmpv = tv[t]; tv[t] = vs; vs = tmpv;
                        int tmpi = tid_[t]; tid_[t] = is; is = tmpi;
                    }
                }
            }
        }
        __syncthreads();
    }

    #pragma unroll
    for (int t = 0; t < TOPK; ++t) {
        cv[tid * TOPK + t] = tv[t];
        ci[tid * TOPK + t] = tid_[t];
    }
    __syncthreads();

    // Merge 8 candidate lists per row; ties -> lower index (matches lax.top_k).
    if (tid < 32) {
        int base = tid * 8 * TOPK;
        for (int s = 0; s < TOPK; ++s) {
            float best = neg_inf(); int bi = 0x7FFFFFFF; int bp = 0;
            for (int p = 0; p < 8 * TOPK; ++p) {
                float v = cv[base + p]; int ii = ci[base + p];
                if (v > best || (v == best && ii < bi)) { best = v; bi = ii; bp = p; }
            }
            cv[base + bp] = neg_inf();
            pb[tid * TOPK + s] = best;
            tix[tid * TOPK + s] = bi;
        }
        // softmax over the 10 (masked entries are exactly 0 -> handled by memset)
        float mx = pb[tid * TOPK];
        float pr[TOPK]; float Z = 0.f;
        #pragma unroll
        for (int s = 0; s < TOPK; ++s) {
            float e = expf(pb[tid * TOPK + s] - mx);
            pr[s] = e; Z += e;
        }
        #pragma unroll
        for (int s = 0; s < TOPK; ++s) pb[tid * TOPK + s] = pr[s] / Z;
    }
    __syncthreads();

    const int q = qt * 32 + r;
    const size_t abase = ((size_t)bh * SS + q) * SS;
    for (int t = slot; t < TOPK; t += 8)
        out_attn[abase + tix[r * TOPK + t]] = pb[r * TOPK + t];

    // context row: 8 columns per thread
    float acc2[8];
    #pragma unroll
    for (int j = 0; j < 8; ++j) acc2[j] = 0.f;
    #pragma unroll
    for (int t = 0; t < TOPK; ++t) {
        float p = pb[r * TOPK + t];
        const float* vr = &Vb[(size_t)tix[r * TOPK + t] * DH + slot * 8];
        float4 v0 = *(const float4*)&vr[0];
        float4 v1 = *(const float4*)&vr[4];
        acc2[0] = fmaf(p, v0.x, acc2[0]); acc2[1] = fmaf(p, v0.y, acc2[1]);
        acc2[2] = fmaf(p, v0.z, acc2[2]); acc2[3] = fmaf(p, v0.w, acc2[3]);
        acc2[4] = fmaf(p, v1.x, acc2[4]); acc2[5] = fmaf(p, v1.y, acc2[5]);
        acc2[6] = fmaf(p, v1.z, acc2[6]); acc2[7] = fmaf(p, v1.w, acc2[7]);
    }
    const int b_ = bh >> 3, h_ = bh & 7;
    float* dst = out_ctx + ((size_t)(b_ * SS + q)) * DD + h_ * DH + slot * 8;
    float4 o0, o1;
    o0.x = acc2[0]; o0.y = acc2[1]; o0.z = acc2[2]; o0.w = acc2[3];
    o1.x = acc2[4]; o1.y = acc2[5]; o1.z = acc2[6]; o1.w = acc2[7];
    *(float4*)&dst[0] = o0;
    *(float4*)&dst[4] = o1;
}

// ---------------------------------------------------------------------------
extern "C" void kernel_launch(void* const* d_in, const int* in_sizes, int n_in,
                              void* d_out, int out_size)
{
    const float* x  = (const float*)d_in[0];
    const float* Wq = (const float*)d_in[1];
    const float* bq = (const float*)d_in[2];
    const float* Wk = (const float*)d_in[3];
    const float* bk = (const float*)d_in[4];
    const float* Wv = (const float*)d_in[5];
    const float* bv = (const float*)d_in[6];

    float* out_ctx  = (float*)d_out;
    float* out_attn = out_ctx + (size_t)BB * SS * DD;

    // attn output is exactly 10 nonzeros/row: zero-fill then scatter.
    cudaMemsetAsync(out_attn, 0, (size_t)BB * HH * SS * SS * sizeof(float));

    dim3 g1(DD / 64, (BB * SS) / 64, 3);   // (8, 128, 3)
    qkv_kernel<<<g1, 256>>>(x, Wq, bq, Wk, bk, Wv, bv);

    dim3 g2(SS / 32, BB * HH);             // (64, 32)
    attn_kernel<<<g2, 256>>>(out_ctx, out_attn);
}

// round 6
// speedup vs baseline: 1.4310x; 1.4310x over previous
#include <cuda_runtime.h>
#include <cstdint>

#define BB 4
#define HH 8
#define SS 2048
#define DD 512
#define DH 64
#define TOPK 10

// Scratch: Q,K transposed [bh][d][s] (d-major for attn GEMM staging);
// V row-major [bh][s][d] (context reads rows).
__device__ float g_Qt[BB*HH*DH*SS];
__device__ float g_Kt[BB*HH*DH*SS];
__device__ float g_V [BB*HH*SS*DH];

__device__ __forceinline__ float neg_inf() { return __int_as_float(0xff800000); }

// ---------------------------------------------------------------------------
// Kernel 1: Y = x @ W^T + b; Q,K scattered transposed, V row-major.
// Serial ascending-k FMA chain per output (bit-exact, matches reference).
// ---------------------------------------------------------------------------
__global__ __launch_bounds__(256) void qkv_kernel(
    const float* __restrict__ x,
    const float* __restrict__ Wq, const float* __restrict__ bq,
    const float* __restrict__ Wk, const float* __restrict__ bk,
    const float* __restrict__ Wv, const float* __restrict__ bv)
{
    const int which = blockIdx.z;
    const float* __restrict__ W    = (which == 0) ? Wq : (which == 1) ? Wk : Wv;
    const float* __restrict__ bias = (which == 0) ? bq : (which == 1) ? bk : bv;

    __shared__ float As[16][68];   // [k][m], padded
    __shared__ float Bs[16][68];   // [k][n], padded

    const int tid = threadIdx.x;
    const int tx  = tid & 15;       // 0..15 -> n
    const int ty  = tid >> 4;       // 0..15 -> m
    const int m0  = blockIdx.y * 64;
    const int n0  = blockIdx.x * 64;   // one head per n-tile (DH==64)

    const int lrow = tid >> 2;      // 0..63
    const int lk4  = tid & 3;       // 0..3

    float c[4][4];
    #pragma unroll
    for (int i = 0; i < 4; ++i)
        #pragma unroll
        for (int j = 0; j < 4; ++j) c[i][j] = 0.f;

    for (int kt = 0; kt < DD / 16; ++kt) {
        float4 av = *(const float4*)&x[(size_t)(m0 + lrow) * DD + kt * 16 + lk4 * 4];
        float4 bv4 = *(const float4*)&W[(size_t)(n0 + lrow) * DD + kt * 16 + lk4 * 4];
        __syncthreads();
        As[lk4 * 4 + 0][lrow] = av.x;
        As[lk4 * 4 + 1][lrow] = av.y;
        As[lk4 * 4 + 2][lrow] = av.z;
        As[lk4 * 4 + 3][lrow] = av.w;
        Bs[lk4 * 4 + 0][lrow] = bv4.x;
        Bs[lk4 * 4 + 1][lrow] = bv4.y;
        Bs[lk4 * 4 + 2][lrow] = bv4.z;
        Bs[lk4 * 4 + 3][lrow] = bv4.w;
        __syncthreads();
        // k ascending; each c[i][j] is one serial FMA chain over all 512 k.
        #pragma unroll
        for (int k = 0; k < 16; ++k) {
            float4 a  = *(const float4*)&As[k][ty * 4];
            float4 b4 = *(const float4*)&Bs[k][tx * 4];
            c[0][0] = fmaf(a.x, b4.x, c[0][0]); c[0][1] = fmaf(a.x, b4.y, c[0][1]);
            c[0][2] = fmaf(a.x, b4.z, c[0][2]); c[0][3] = fmaf(a.x, b4.w, c[0][3]);
            c[1][0] = fmaf(a.y, b4.x, c[1][0]); c[1][1] = fmaf(a.y, b4.y, c[1][1]);
            c[1][2] = fmaf(a.y, b4.z, c[1][2]); c[1][3] = fmaf(a.y, b4.w, c[1][3]);
            c[2][0] = fmaf(a.z, b4.x, c[2][0]); c[2][1] = fmaf(a.z, b4.y, c[2][1]);
            c[2][2] = fmaf(a.z, b4.z, c[2][2]); c[2][3] = fmaf(a.z, b4.w, c[2][3]);
            c[3][0] = fmaf(a.w, b4.x, c[3][0]); c[3][1] = fmaf(a.w, b4.y, c[3][1]);
            c[3][2] = fmaf(a.w, b4.z, c[3][2]); c[3][3] = fmaf(a.w, b4.w, c[3][3]);
        }
    }

    float4 biasv = *(const float4*)&bias[n0 + tx * 4];
    const int head = blockIdx.x;
    #pragma unroll
    for (int i = 0; i < 4; ++i) {
        int m  = m0 + ty * 4 + i;
        int b_ = m >> 11;        // m / 2048
        int s_ = m & 2047;
        float o0 = c[i][0] + biasv.x;
        float o1 = c[i][1] + biasv.y;
        float o2 = c[i][2] + biasv.z;
        float o3 = c[i][3] + biasv.w;
        if (which == 2) {
            float4 o; o.x = o0; o.y = o1; o.z = o2; o.w = o3;
            *(float4*)&g_V[(size_t)(((b_ * HH + head) * SS) + s_) * DH + tx * 4] = o;
        } else {
            float* dst = (which == 0) ? g_Qt : g_Kt;
            size_t base = ((size_t)(b_ * HH + head) * DH + tx * 4) * SS + s_;
            dst[base + 0 * SS] = o0;
            dst[base + 1 * SS] = o1;
            dst[base + 2 * SS] = o2;
            dst[base + 3 * SS] = o3;
        }
    }
}

// ---------------------------------------------------------------------------
// Kernel 2: per (b,h, 32-q-row tile). SGEMM-style score tile: 128 threads,
// each computes a 4q x 4k sub-tile; per d-step 2 LDS.128 -> 16 FMA.
// d-loop strictly serial ascending per accumulator (bit-exact chain).
// Scores dumped to smem per tile; scan phase (4 thr/row x 16 cols)
// maintains per-thread top-10; merge 4 lists/row; softmax over 10;
// scatter attn (rest pre-zeroed); context from V rows.
// ---------------------------------------------------------------------------
__global__ __launch_bounds__(128) void attn_kernel(
    float* __restrict__ out_ctx, float* __restrict__ out_attn)
{
    const int qt  = blockIdx.x;     // 0..63 (32 q-rows each)
    const int bh  = blockIdx.y;     // 0..31
    const int tid = threadIdx.x;    // 0..127
    const int ty  = tid >> 4;       // 0..7  -> q rows ty*4..+3
    const int tx  = tid & 15;       // 0..15 -> k cols tx*4..+3
    const int srow = tid >> 2;      // 0..31 scan row
    const int scg  = tid & 3;       // 0..3  scan col group (16 cols)

    __shared__ float As[64 * 36];        // Q  [d][m], m-padded 32->36
    __shared__ float Bs[64 * 68];        // K  [d][n], n-padded 64->68
    __shared__ float Sc[32 * 68];        // scores [q][k] per tile
    __shared__ float cv[128 * TOPK];     // per-thread candidates (values)
    __shared__ int   ci[128 * TOPK];     // per-thread candidates (indices)
    __shared__ float pb[32 * TOPK];      // per-row probs
    __shared__ int   tix[32 * TOPK];     // per-row indices

    const float* __restrict__ Qt = g_Qt + (size_t)bh * DH * SS;
    const float* __restrict__ Kt = g_Kt + (size_t)bh * DH * SS;
    const float* __restrict__ Vb = g_V  + (size_t)bh * SS * DH;

    // Stage As = Q^T tile (64d x 32m), scaled by 1/8 (exact pow2).
    #pragma unroll
    for (int p = 0; p < 4; ++p) {
        int idx = p * 128 + tid;        // 0..511 float4s
        int d   = idx >> 3;
        int mf4 = idx & 7;
        float4 v = *(const float4*)&Qt[(size_t)d * SS + qt * 32 + mf4 * 4];
        v.x *= 0.125f; v.y *= 0.125f; v.z *= 0.125f; v.w *= 0.125f;
        *(float4*)&As[d * 36 + mf4 * 4] = v;
    }

    float tv[TOPK];
    int   ti[TOPK];
    #pragma unroll
    for (int t = 0; t < TOPK; ++t) { tv[t] = neg_inf(); ti[t] = 0x7FFFFFFF; }

    for (int kt = 0; kt < SS / 64; ++kt) {
        // Stage Bs = K^T tile (64d x 64n), coalesced rows.
        #pragma unroll
        for (int p = 0; p < 8; ++p) {
            int idx = p * 128 + tid;    // 0..1023 float4s
            int d   = idx >> 4;
            int nf4 = idx & 15;
            *(float4*)&Bs[d * 68 + nf4 * 4] =
                *(const float4*)&Kt[(size_t)d * SS + kt * 64 + nf4 * 4];
        }
        __syncthreads();                 // Bs ready (also: prior scan done before new dump)

        // GEMM: 4x4 accumulators, d ascending serial per accumulator.
        float a0[4], a1[4], a2[4], a3[4];
        #pragma unroll
        for (int j = 0; j < 4; ++j) { a0[j]=0.f; a1[j]=0.f; a2[j]=0.f; a3[j]=0.f; }
        #pragma unroll 8
        for (int d = 0; d < 64; ++d) {
            float4 q = *(const float4*)&As[d * 36 + ty * 4];
            float4 k = *(const float4*)&Bs[d * 68 + tx * 4];
            a0[0]=fmaf(q.x,k.x,a0[0]); a0[1]=fmaf(q.x,k.y,a0[1]);
            a0[2]=fmaf(q.x,k.z,a0[2]); a0[3]=fmaf(q.x,k.w,a0[3]);
            a1[0]=fmaf(q.y,k.x,a1[0]); a1[1]=fmaf(q.y,k.y,a1[1]);
            a1[2]=fmaf(q.y,k.z,a1[2]); a1[3]=fmaf(q.y,k.w,a1[3]);
            a2[0]=fmaf(q.z,k.x,a2[0]); a2[1]=fmaf(q.z,k.y,a2[1]);
            a2[2]=fmaf(q.z,k.z,a2[2]); a2[3]=fmaf(q.z,k.w,a2[3]);
            a3[0]=fmaf(q.w,k.x,a3[0]); a3[1]=fmaf(q.w,k.y,a3[1]);
            a3[2]=fmaf(q.w,k.z,a3[2]); a3[3]=fmaf(q.w,k.w,a3[3]);
        }
        // Dump scores to smem.
        *(float4*)&Sc[(ty*4+0)*68 + tx*4] = make_float4(a0[0],a0[1],a0[2],a0[3]);
        *(float4*)&Sc[(ty*4+1)*68 + tx*4] = make_float4(a1[0],a1[1],a1[2],a1[3]);
        *(float4*)&Sc[(ty*4+2)*68 + tx*4] = make_float4(a2[0],a2[1],a2[2],a2[3]);
        *(float4*)&Sc[(ty*4+3)*68 + tx*4] = make_float4(a3[0],a3[1],a3[2],a3[3]);
        __syncthreads();                 // Sc ready; GEMM done (Bs free to restage)

        // Scan: this thread's 16 columns of its row, ascending k.
        #pragma unroll
        for (int j4 = 0; j4 < 4; ++j4) {
            float4 s = *(const float4*)&Sc[srow * 68 + scg * 16 + j4 * 4];
            int k0 = kt * 64 + scg * 16 + j4 * 4;
            float sv[4] = {s.x, s.y, s.z, s.w};
            #pragma unroll
            for (int e = 0; e < 4; ++e) {
                if (sv[e] > tv[TOPK - 1]) {
                    float vs = sv[e]; int is = k0 + e;
                    #pragma unroll
                    for (int t = 0; t < TOPK; ++t) {
                        if (vs > tv[t]) {
                            float tmpv = tv[t]; tv[t] = vs; vs = tmpv;
                            int tmpi = ti[t]; ti[t] = is; is = tmpi;
                        }
                    }
                }
            }
        }
    }

    #pragma unroll
    for (int t = 0; t < TOPK; ++t) {
        cv[tid * TOPK + t] = tv[t];
        ci[tid * TOPK + t] = ti[t];
    }
    __syncthreads();

    // Merge 4 candidate lists per row; ties -> lower index (lax.top_k).
    if (tid < 32) {
        int base = tid * 4 * TOPK;
        for (int s = 0; s < TOPK; ++s) {
            float best = neg_inf(); int bi = 0x7FFFFFFF; int bp = 0;
            for (int p = 0; p < 4 * TOPK; ++p) {
                float v = cv[base + p]; int ii = ci[base + p];
                if (v > best || (v == best && ii < bi)) { best = v; bi = ii; bp = p; }
            }
            cv[base + bp] = neg_inf();
            pb[tid * TOPK + s] = best;
            tix[tid * TOPK + s] = bi;
        }
        float mx = pb[tid * TOPK];
        float pr[TOPK]; float Z = 0.f;
        #pragma unroll
        for (int s = 0; s < TOPK; ++s) {
            float e = expf(pb[tid * TOPK + s] - mx);
            pr[s] = e; Z += e;
        }
        #pragma unroll
        for (int s = 0; s < TOPK; ++s) pb[tid * TOPK + s] = pr[s] / Z;
    }
    __syncthreads();

    const int q = qt * 32 + srow;
    const size_t abase = ((size_t)bh * SS + q) * SS;
    for (int t = scg; t < TOPK; t += 4)
        out_attn[abase + tix[srow * TOPK + t]] = pb[srow * TOPK + t];

    // Context: 4 threads per row, 16 dh-columns each.
    float acc[16];
    #pragma unroll
    for (int j = 0; j < 16; ++j) acc[j] = 0.f;
    #pragma unroll
    for (int t = 0; t < TOPK; ++t) {
        float p = pb[srow * TOPK + t];
        const float* vr = &Vb[(size_t)tix[srow * TOPK + t] * DH + scg * 16];
        #pragma unroll
        for (int j4 = 0; j4 < 4; ++j4) {
            float4 v = *(const float4*)&vr[j4 * 4];
            acc[j4*4+0] = fmaf(p, v.x, acc[j4*4+0]);
            acc[j4*4+1] = fmaf(p, v.y, acc[j4*4+1]);
            acc[j4*4+2] = fmaf(p, v.z, acc[j4*4+2]);
            acc[j4*4+3] = fmaf(p, v.w, acc[j4*4+3]);
        }
    }
    const int b_ = bh >> 3, h_ = bh & 7;
    float* dst = out_ctx + ((size_t)(b_ * SS + q)) * DD + h_ * DH + scg * 16;
    #pragma unroll
    for (int j4 = 0; j4 < 4; ++j4) {
        float4 o;
        o.x = acc[j4*4+0]; o.y = acc[j4*4+1];
        o.z = acc[j4*4+2]; o.w = acc[j4*4+3];
        *(float4*)&dst[j4 * 4] = o;
    }
}

// ---------------------------------------------------------------------------
extern "C" void kernel_launch(void* const* d_in, const int* in_sizes, int n_in,
                              void* d_out, int out_size)
{
    const float* x  = (const float*)d_in[0];
    const float* Wq = (const float*)d_in[1];
    const float* bq = (const float*)d_in[2];
    const float* Wk = (const float*)d_in[3];
    const float* bk = (const float*)d_in[4];
    const float* Wv = (const float*)d_in[5];
    const float* bv = (const float*)d_in[6];

    float* out_ctx  = (float*)d_out;
    float* out_attn = out_ctx + (size_t)BB * SS * DD;

    // attn output is exactly 10 nonzeros/row: zero-fill then scatter.
    cudaMemsetAsync(out_attn, 0, (size_t)BB * HH * SS * SS * sizeof(float));

    dim3 g1(DD / 64, (BB * SS) / 64, 3);   // (8, 128, 3)
    qkv_kernel<<<g1, 256>>>(x, Wq, bq, Wk, bk, Wv, bv);

    dim3 g2(SS / 32, BB * HH);             // (64, 32)
    attn_kernel<<<g2, 128>>>(out_ctx, out_attn);
}